// round 10
// baseline (speedup 1.0000x reference)
#include <cuda_runtime.h>
#include <cuda_bf16.h>
#include <math.h>
#include <stdint.h>

// x[131072,256] @ W1[256,512] -> tanh -> @W2[512,512] -> tanh -> @W3[512,128] (+biases).
// Fixed-point loop converges to F(x) within ~4e-7 abs => output == MLP forward.
constexpr int BATCH = 131072;
constexpr int DIN   = 256;
constexpr int HID   = 512;
constexpr int DOUT  = 128;

// ---------- device scratch (static; no runtime allocation allowed) ----------
__device__ __align__(256) __nv_bfloat16 g_xh[(size_t)BATCH * DIN];
__device__ __align__(256) __nv_bfloat16 g_xl[(size_t)BATCH * DIN];
__device__ __align__(256) __nv_bfloat16 g_h1h[(size_t)BATCH * HID];
__device__ __align__(256) __nv_bfloat16 g_h1l[(size_t)BATCH * HID];
__device__ __align__(256) __nv_bfloat16 g_h2h[(size_t)BATCH * HID];
__device__ __align__(256) __nv_bfloat16 g_h2l[(size_t)BATCH * HID];

constexpr size_t W1_OFF = 0;
constexpr size_t W1_SZ  = (size_t)HID * DIN;
constexpr size_t W2_OFF = W1_OFF + W1_SZ;
constexpr size_t W2_SZ  = (size_t)HID * HID;
constexpr size_t W3_OFF = W2_OFF + W2_SZ;
constexpr size_t W3_SZ  = (size_t)DOUT * HID;
__device__ __align__(256) __nv_bfloat16 g_wh[W1_SZ + W2_SZ + W3_SZ];
__device__ __align__(256) __nv_bfloat16 g_wl[W1_SZ + W2_SZ + W3_SZ];

// ---------- PTX helpers (compute_103-safe: NO tcgen05) ----------
__device__ __forceinline__ uint32_t smem_u32(const void* p) {
    uint32_t a;
    asm("{ .reg .u64 t; cvta.to.shared.u64 t, %1; cvt.u32.u64 %0, t; }" : "=r"(a) : "l"(p));
    return a;
}
__device__ __forceinline__ void cp16(uint32_t dst, const void* src) {
    asm volatile("cp.async.cg.shared.global [%0], [%1], 16;" :: "r"(dst), "l"(src));
}
__device__ __forceinline__ void cp_commit() { asm volatile("cp.async.commit_group;"); }
__device__ __forceinline__ void cp_wait1()  { asm volatile("cp.async.wait_group 1;"); }

__device__ __forceinline__ void ldsm4(uint32_t* r, uint32_t addr) {
    asm volatile("ldmatrix.sync.aligned.m8n8.x4.shared.b16 {%0,%1,%2,%3}, [%4];"
                 : "=r"(r[0]), "=r"(r[1]), "=r"(r[2]), "=r"(r[3]) : "r"(addr));
}
__device__ __forceinline__ void mma16816(float* d, const uint32_t* a, const uint32_t* b) {
    asm volatile("mma.sync.aligned.m16n8k16.row.col.f32.bf16.bf16.f32 "
                 "{%0,%1,%2,%3}, {%4,%5,%6,%7}, {%8,%9}, {%0,%1,%2,%3};"
                 : "+f"(d[0]), "+f"(d[1]), "+f"(d[2]), "+f"(d[3])
                 : "r"(a[0]), "r"(a[1]), "r"(a[2]), "r"(a[3]), "r"(b[0]), "r"(b[1]));
}

// fast accurate tanh: (e-1)/(e+1), e = 2^(2x*log2e). abs err ~1e-7.
__device__ __forceinline__ float tanh_fast(float x) {
    float xc = fminf(fmaxf(x, -15.0f), 15.0f);
    float e;
    asm("ex2.approx.f32 %0, %1;" : "=f"(e) : "f"(xc * 2.885390081777927f));
    float r;
    asm("rcp.approx.f32 %0, %1;" : "=f"(r) : "f"(e + 1.0f));
    return (e - 1.0f) * r;
}

__device__ __forceinline__ void split2(float v0, float v1, uint32_t& hi, uint32_t& lo) {
    __nv_bfloat16 h0 = __float2bfloat16(v0);
    __nv_bfloat16 h1 = __float2bfloat16(v1);
    __nv_bfloat16 l0 = __float2bfloat16(v0 - __bfloat162float(h0));
    __nv_bfloat16 l1 = __float2bfloat16(v1 - __bfloat162float(h1));
    hi = (uint32_t)__bfloat16_as_ushort(h0) | ((uint32_t)__bfloat16_as_ushort(h1) << 16);
    lo = (uint32_t)__bfloat16_as_ushort(l0) | ((uint32_t)__bfloat16_as_ushort(l1) << 16);
}

// ---------- merged prep: x split + all W split/transpose in ONE launch ----------
constexpr int XB = (int)((size_t)BATCH * DIN / 4 / 256);          // 32768
constexpr int WTOT = (int)(W1_SZ + W2_SZ + W3_SZ);                // 458752
constexpr int WB = (WTOT + 255) / 256;                            // 1792

__global__ void prep_all(const float* __restrict__ x,
                         const float* __restrict__ W1,
                         const float* __restrict__ W2,
                         const float* __restrict__ W3)
{
    int b = blockIdx.x;
    if (b < XB) {
        size_t i = ((size_t)b * 256 + threadIdx.x) * 4;
        float4 v = *reinterpret_cast<const float4*>(x + i);
        uint2 hi, lo;
        split2(v.x, v.y, hi.x, lo.x);
        split2(v.z, v.w, hi.y, lo.y);
        *reinterpret_cast<uint2*>(&g_xh[i]) = hi;
        *reinterpret_cast<uint2*>(&g_xl[i]) = lo;
    } else {
        int idx = (b - XB) * 256 + threadIdx.x;
        if (idx >= WTOT) return;
        const float* W; int K, N, loc;
        if (idx < (int)W2_OFF)      { W = W1; K = DIN; N = HID;  loc = idx; }
        else if (idx < (int)W3_OFF) { W = W2; K = HID; N = HID;  loc = idx - (int)W2_OFF; }
        else                        { W = W3; K = HID; N = DOUT; loc = idx - (int)W3_OFF; }
        int n = loc / K;
        int k = loc - n * K;
        float v = W[(size_t)k * N + n];
        __nv_bfloat16 h = __float2bfloat16(v);
        g_wh[idx] = h;
        g_wl[idx] = __float2bfloat16(v - __bfloat162float(h));
    }
}

// ---------- main GEMM: 128x128 tile, BK=32, 3-stage cp.async, single sync/iter ----------
// SMEM per stage: AH 8KB | AL 8KB | BH 8KB | BL 8KB = 32KB; 3 stages = 96KB -> 2 CTAs/SM.
// R10 changes vs R9: (1) loop-invariant 64-bit row-base offsets (kills per-chunk IMAD.WIDE
// chains that showed as alu=20.6%); (2) ALL 32 LDSM issued up front per ks-step (bl in its
// own regs) so the 48 MMAs run without an interior LDS latency bubble.
constexpr uint32_t OFF_AH = 0;
constexpr uint32_t OFF_AL = 8192;
constexpr uint32_t OFF_BH = 16384;
constexpr uint32_t OFF_BL = 24576;
constexpr uint32_t STAGE  = 32768;
constexpr int SMEM_TOTAL  = 3 * STAGE;   // 96KB -> 2 CTAs/SM

template<bool TANH, bool FP32OUT>
__global__ __launch_bounds__(256, 2)
void gemm_hmma(int aSel, size_t wOff, const float* __restrict__ bias,
               int cSel, float* __restrict__ Cf, int N, int K)
{
    const __nv_bfloat16 *Ah, *Al;
    if      (aSel == 0) { Ah = g_xh;  Al = g_xl;  }
    else if (aSel == 1) { Ah = g_h1h; Al = g_h1l; }
    else                { Ah = g_h2h; Al = g_h2l; }
    __nv_bfloat16 *Ch = nullptr, *Cl = nullptr;
    if      (cSel == 1) { Ch = g_h1h; Cl = g_h1l; }
    else if (cSel == 2) { Ch = g_h2h; Cl = g_h2l; }
    const __nv_bfloat16* Wh = g_wh + wOff;
    const __nv_bfloat16* Wl = g_wl + wOff;

    extern __shared__ char smem[];
    const uint32_t sbase = smem_u32(smem);
    const int tid  = threadIdx.x;
    const int wid  = tid >> 5;
    const int lane = tid & 31;
    const int mBase = blockIdx.y * 128;
    const int nBase = blockIdx.x * 128;
    const int warpM = (wid >> 1) * 32;
    const int warpN = (wid & 1) * 64;
    const int NC = K / 32;

    // ---- loader mapping: precompute loop-invariant row bases (no per-chunk IMAD.WIDE) ----
    const int lr = tid >> 2;               // 0..63
    const int lj = tid & 3;
    const uint32_t swj = (uint32_t)lj * 16;
    auto so = [&](uint32_t row) { return row * 64 + (swj ^ ((row & 6) << 3)); };
    const uint32_t soA0 = so((uint32_t)lr),      soA1 = so((uint32_t)(lr + 64));
    const size_t jcol = (size_t)lj * 8;
    const size_t gA0 = (size_t)(mBase + lr) * K + jcol;
    const size_t gA1 = (size_t)(mBase + lr + 64) * K + jcol;
    const size_t gB0 = (size_t)(nBase + lr) * K + jcol;
    const size_t gB1 = (size_t)(nBase + lr + 64) * K + jcol;

    auto loadChunk = [&](int kc, int s) {
        const uint32_t sb = sbase + (uint32_t)s * STAGE;
        const size_t co = (size_t)kc * 32;
        cp16(sb + OFF_AH + soA0, Ah + gA0 + co);
        cp16(sb + OFF_AH + soA1, Ah + gA1 + co);
        cp16(sb + OFF_AL + soA0, Al + gA0 + co);
        cp16(sb + OFF_AL + soA1, Al + gA1 + co);
        cp16(sb + OFF_BH + soA0, Wh + gB0 + co);
        cp16(sb + OFF_BH + soA1, Wh + gB1 + co);
        cp16(sb + OFF_BL + soA0, Wl + gB0 + co);
        cp16(sb + OFF_BL + soA1, Wl + gB1 + co);
    };

    float acc[2][8][4];
    #pragma unroll
    for (int i = 0; i < 2; i++)
        #pragma unroll
        for (int j = 0; j < 8; j++)
            #pragma unroll
            for (int q = 0; q < 4; q++) acc[i][j][q] = 0.0f;

    const int lrow = lane & 15, lhi = lane >> 4;

    // ---- hoisted fragment smem-offset components (row parts are loop-invariant) ----
    uint32_t aRow[2], aSw[2], bRow[4], bSw[4];
    #pragma unroll
    for (int i = 0; i < 2; i++) {
        uint32_t row = warpM + i * 16 + lrow;
        aRow[i] = row * 64; aSw[i] = (row & 6) << 3;
    }
    #pragma unroll
    for (int p = 0; p < 4; p++) {
        uint32_t row = warpN + p * 16 + lrow;
        bRow[p] = row * 64; bSw[p] = (row & 6) << 3;
    }

    loadChunk(0, 0); cp_commit();
    loadChunk(1, 1); cp_commit();

    for (int c = 0; c < NC; c++) {
        cp_wait1();
        __syncthreads();
        if (c + 2 < NC) loadChunk(c + 2, (c + 2) % 3);
        cp_commit();

        const uint32_t sb = sbase + (uint32_t)(c % 3) * STAGE;
        #pragma unroll
        for (int ks = 0; ks < 2; ks++) {
            const uint32_t colb = ks * 32 + lhi * 16;
            uint32_t ah[2][4], al[2][4], bb[8][2], bl[8][2];
            // ---- all 32 LDSM up front ----
            #pragma unroll
            for (int i = 0; i < 2; i++) {
                uint32_t off = aRow[i] + (colb ^ aSw[i]);
                ldsm4(ah[i], sb + OFF_AH + off);
                ldsm4(al[i], sb + OFF_AL + off);
            }
            #pragma unroll
            for (int p = 0; p < 4; p++) {
                uint32_t off = bRow[p] + (colb ^ bSw[p]);
                uint32_t r[4];
                ldsm4(r, sb + OFF_BH + off);
                bb[2 * p][0] = r[0]; bb[2 * p][1] = r[2];
                bb[2 * p + 1][0] = r[1]; bb[2 * p + 1][1] = r[3];
                uint32_t q[4];
                ldsm4(q, sb + OFF_BL + off);
                bl[2 * p][0] = q[0]; bl[2 * p][1] = q[2];
                bl[2 * p + 1][0] = q[1]; bl[2 * p + 1][1] = q[3];
            }
            // ---- 48 MMAs back-to-back ----
            #pragma unroll
            for (int i = 0; i < 2; i++)
                #pragma unroll
                for (int j = 0; j < 8; j++) mma16816(acc[i][j], ah[i], bb[j]);
            #pragma unroll
            for (int i = 0; i < 2; i++)
                #pragma unroll
                for (int j = 0; j < 8; j++) mma16816(acc[i][j], al[i], bb[j]);
            #pragma unroll
            for (int i = 0; i < 2; i++)
                #pragma unroll
                for (int j = 0; j < 8; j++) mma16816(acc[i][j], ah[i], bl[j]);
        }
    }

    // ---------- epilogue ----------
    #pragma unroll
    for (int i = 0; i < 2; i++) {
        const int m0 = mBase + warpM + i * 16 + (lane >> 2);
        #pragma unroll
        for (int j = 0; j < 8; j++) {
            const int n = nBase + warpN + j * 8 + (lane & 3) * 2;
            const float2 bb2 = *reinterpret_cast<const float2*>(&bias[n]);
            float v00 = acc[i][j][0] + bb2.x, v01 = acc[i][j][1] + bb2.y;
            float v10 = acc[i][j][2] + bb2.x, v11 = acc[i][j][3] + bb2.y;
            if (TANH) {
                v00 = tanh_fast(v00); v01 = tanh_fast(v01);
                v10 = tanh_fast(v10); v11 = tanh_fast(v11);
            }
            if (FP32OUT) {
                *reinterpret_cast<float2*>(&Cf[(size_t)m0 * N + n])       = make_float2(v00, v01);
                *reinterpret_cast<float2*>(&Cf[(size_t)(m0 + 8) * N + n]) = make_float2(v10, v11);
            } else {
                uint32_t hi, lo;
                split2(v00, v01, hi, lo);
                *reinterpret_cast<uint32_t*>(&Ch[(size_t)m0 * N + n]) = hi;
                *reinterpret_cast<uint32_t*>(&Cl[(size_t)m0 * N + n]) = lo;
                split2(v10, v11, hi, lo);
                *reinterpret_cast<uint32_t*>(&Ch[(size_t)(m0 + 8) * N + n]) = hi;
                *reinterpret_cast<uint32_t*>(&Cl[(size_t)(m0 + 8) * N + n]) = lo;
            }
        }
    }
}

// ---------- launch ----------
extern "C" void kernel_launch(void* const* d_in, const int* in_sizes, int n_in,
                              void* d_out, int out_size)
{
    const float* x  = (const float*)d_in[0];
    const float* W1 = (const float*)d_in[1];
    const float* b1 = (const float*)d_in[2];
    const float* W2 = (const float*)d_in[3];
    const float* b2 = (const float*)d_in[4];
    const float* W3 = (const float*)d_in[5];
    const float* b3 = (const float*)d_in[6];
    float* out = (float*)d_out;

    prep_all<<<XB + WB, 256>>>(x, W1, W2, W3);

    cudaFuncSetAttribute(gemm_hmma<true,  false>,
                         cudaFuncAttributeMaxDynamicSharedMemorySize, SMEM_TOTAL);
    cudaFuncSetAttribute(gemm_hmma<false, true>,
                         cudaFuncAttributeMaxDynamicSharedMemorySize, SMEM_TOTAL);

    dim3 grid12(HID / 128, BATCH / 128);   // (4, 1024)
    dim3 grid3 (DOUT / 128, BATCH / 128);  // (1, 1024)

    gemm_hmma<true,  false><<<grid12, 256, SMEM_TOTAL>>>(0, W1_OFF, b1, 1, nullptr, HID, DIN);
    gemm_hmma<true,  false><<<grid12, 256, SMEM_TOTAL>>>(1, W2_OFF, b2, 2, nullptr, HID, HID);
    gemm_hmma<false, true ><<<grid3,  256, SMEM_TOTAL>>>(2, W3_OFF, b3, 0, out, DOUT, HID);
}

// round 12
// speedup vs baseline: 1.3210x; 1.3210x over previous
#include <cuda_runtime.h>
#include <cuda_fp16.h>
#include <math.h>
#include <stdint.h>

// x[131072,256] @ W1[256,512] -> tanh -> @W2[512,512] -> tanh -> @W3[512,128] (+biases).
// Fixed-point loop converges to F(x) within ~4e-7 abs => output == MLP forward.
//
// Numerics (calibrated on R3/R9 measurements, theory->measured factor 1.53):
//   A (activations) split into fp16 hi+lo  -> A-side error ~2^-22 (negligible)
//   B (weights) single fp16                -> 2.8e-4 rms/layer -> ~6e-4 total (< 1e-3 gate)
// 2 MMA terms per fragment instead of 3 -> 33% less tensor work than bf16 3-term.
constexpr int BATCH = 131072;
constexpr int DIN   = 256;
constexpr int HID   = 512;
constexpr int DOUT  = 128;

// ---------- device scratch (static; no runtime allocation allowed) ----------
__device__ __align__(256) __half g_xh[(size_t)BATCH * DIN];
__device__ __align__(256) __half g_xl[(size_t)BATCH * DIN];
__device__ __align__(256) __half g_h1h[(size_t)BATCH * HID];
__device__ __align__(256) __half g_h1l[(size_t)BATCH * HID];
__device__ __align__(256) __half g_h2h[(size_t)BATCH * HID];
__device__ __align__(256) __half g_h2l[(size_t)BATCH * HID];

constexpr size_t W1_OFF = 0;
constexpr size_t W1_SZ  = (size_t)HID * DIN;
constexpr size_t W2_OFF = W1_OFF + W1_SZ;
constexpr size_t W2_SZ  = (size_t)HID * HID;
constexpr size_t W3_OFF = W2_OFF + W2_SZ;
constexpr size_t W3_SZ  = (size_t)DOUT * HID;
__device__ __align__(256) __half g_w[W1_SZ + W2_SZ + W3_SZ];   // single fp16 weights [N,K]

// ---------- PTX helpers (compute_103-safe: NO tcgen05) ----------
__device__ __forceinline__ uint32_t smem_u32(const void* p) {
    uint32_t a;
    asm("{ .reg .u64 t; cvta.to.shared.u64 t, %1; cvt.u32.u64 %0, t; }" : "=r"(a) : "l"(p));
    return a;
}
__device__ __forceinline__ void cp16(uint32_t dst, const void* src) {
    asm volatile("cp.async.cg.shared.global [%0], [%1], 16;" :: "r"(dst), "l"(src));
}
__device__ __forceinline__ void cp_commit() { asm volatile("cp.async.commit_group;"); }
__device__ __forceinline__ void cp_wait1()  { asm volatile("cp.async.wait_group 1;"); }

__device__ __forceinline__ void ldsm4(uint32_t* r, uint32_t addr) {
    asm volatile("ldmatrix.sync.aligned.m8n8.x4.shared.b16 {%0,%1,%2,%3}, [%4];"
                 : "=r"(r[0]), "=r"(r[1]), "=r"(r[2]), "=r"(r[3]) : "r"(addr));
}
__device__ __forceinline__ void mma16816(float* d, const uint32_t* a, const uint32_t* b) {
    asm volatile("mma.sync.aligned.m16n8k16.row.col.f32.f16.f16.f32 "
                 "{%0,%1,%2,%3}, {%4,%5,%6,%7}, {%8,%9}, {%0,%1,%2,%3};"
                 : "+f"(d[0]), "+f"(d[1]), "+f"(d[2]), "+f"(d[3])
                 : "r"(a[0]), "r"(a[1]), "r"(a[2]), "r"(a[3]), "r"(b[0]), "r"(b[1]));
}

// fast accurate tanh: (e-1)/(e+1), e = 2^(2x*log2e). abs err ~1e-7.
__device__ __forceinline__ float tanh_fast(float x) {
    float xc = fminf(fmaxf(x, -15.0f), 15.0f);
    float e;
    asm("ex2.approx.f32 %0, %1;" : "=f"(e) : "f"(xc * 2.885390081777927f));
    float r;
    asm("rcp.approx.f32 %0, %1;" : "=f"(r) : "f"(e + 1.0f));
    return (e - 1.0f) * r;
}

// split two floats into fp16 hi pair + fp16 lo-residual pair (packed b32)
__device__ __forceinline__ void split2h(float v0, float v1, uint32_t& hi, uint32_t& lo) {
    __half h0 = __float2half_rn(v0);
    __half h1 = __float2half_rn(v1);
    __half l0 = __float2half_rn(v0 - __half2float(h0));
    __half l1 = __float2half_rn(v1 - __half2float(h1));
    hi = (uint32_t)__half_as_ushort(h0) | ((uint32_t)__half_as_ushort(h1) << 16);
    lo = (uint32_t)__half_as_ushort(l0) | ((uint32_t)__half_as_ushort(l1) << 16);
}

// ---------- merged prep: x split + all W convert/transpose in ONE launch ----------
constexpr int XB = (int)((size_t)BATCH * DIN / 4 / 256);          // 32768
constexpr int WTOT = (int)(W1_SZ + W2_SZ + W3_SZ);                // 458752
constexpr int WB = (WTOT + 255) / 256;                            // 1792

__global__ void prep_all(const float* __restrict__ x,
                         const float* __restrict__ W1,
                         const float* __restrict__ W2,
                         const float* __restrict__ W3)
{
    int b = blockIdx.x;
    if (b < XB) {
        size_t i = ((size_t)b * 256 + threadIdx.x) * 4;
        float4 v = *reinterpret_cast<const float4*>(x + i);
        uint2 hi, lo;
        split2h(v.x, v.y, hi.x, lo.x);
        split2h(v.z, v.w, hi.y, lo.y);
        *reinterpret_cast<uint2*>(&g_xh[i]) = hi;
        *reinterpret_cast<uint2*>(&g_xl[i]) = lo;
    } else {
        int idx = (b - XB) * 256 + threadIdx.x;
        if (idx >= WTOT) return;
        const float* W; int K, N, loc;
        if (idx < (int)W2_OFF)      { W = W1; K = DIN; N = HID;  loc = idx; }
        else if (idx < (int)W3_OFF) { W = W2; K = HID; N = HID;  loc = idx - (int)W2_OFF; }
        else                        { W = W3; K = HID; N = DOUT; loc = idx - (int)W3_OFF; }
        int n = loc / K;
        int k = loc - n * K;
        g_w[idx] = __float2half_rn(W[(size_t)k * N + n]);
    }
}

// ---------- main GEMM: 128x128 tile, BK=32, 3-stage cp.async, single sync/iter ----------
// SMEM per stage: AH 8KB | AL 8KB | B 8KB = 24KB; 3 stages = 72KB -> 2 CTAs/SM.
// 2 MMA terms per ks-step: (ah + al) * b, fp32 accumulate.
constexpr uint32_t OFF_AH = 0;
constexpr uint32_t OFF_AL = 8192;
constexpr uint32_t OFF_B  = 16384;
constexpr uint32_t STAGE  = 24576;
constexpr int SMEM_TOTAL  = 3 * STAGE;   // 73728 (72KB) -> 2 CTAs/SM

template<bool TANH, bool FP32OUT>
__global__ __launch_bounds__(256, 2)
void gemm_hmma(int aSel, size_t wOff, const float* __restrict__ bias,
               int cSel, float* __restrict__ Cf, int N, int K)
{
    const __half *Ah, *Al;
    if      (aSel == 0) { Ah = g_xh;  Al = g_xl;  }
    else if (aSel == 1) { Ah = g_h1h; Al = g_h1l; }
    else                { Ah = g_h2h; Al = g_h2l; }
    __half *Ch = nullptr, *Cl = nullptr;
    if      (cSel == 1) { Ch = g_h1h; Cl = g_h1l; }
    else if (cSel == 2) { Ch = g_h2h; Cl = g_h2l; }
    const __half* W = g_w + wOff;

    extern __shared__ char smem[];
    const uint32_t sbase = smem_u32(smem);
    const int tid  = threadIdx.x;
    const int wid  = tid >> 5;
    const int lane = tid & 31;
    const int mBase = blockIdx.y * 128;
    const int nBase = blockIdx.x * 128;
    const int warpM = (wid >> 1) * 32;
    const int warpN = (wid & 1) * 64;
    const int NC = K / 32;

    // ---- loader mapping: loop-invariant row bases ----
    const int lr = tid >> 2;               // 0..63
    const int lj = tid & 3;
    const uint32_t swj = (uint32_t)lj * 16;
    auto so = [&](uint32_t row) { return row * 64 + (swj ^ ((row & 6) << 3)); };
    const uint32_t soA0 = so((uint32_t)lr), soA1 = so((uint32_t)(lr + 64));
    const size_t jcol = (size_t)lj * 8;
    const size_t gA0 = (size_t)(mBase + lr) * K + jcol;
    const size_t gA1 = (size_t)(mBase + lr + 64) * K + jcol;
    const size_t gB0 = (size_t)(nBase + lr) * K + jcol;
    const size_t gB1 = (size_t)(nBase + lr + 64) * K + jcol;

    auto loadChunk = [&](int kc, int s) {
        const uint32_t sb = sbase + (uint32_t)s * STAGE;
        const size_t co = (size_t)kc * 32;
        cp16(sb + OFF_AH + soA0, Ah + gA0 + co);
        cp16(sb + OFF_AH + soA1, Ah + gA1 + co);
        cp16(sb + OFF_AL + soA0, Al + gA0 + co);
        cp16(sb + OFF_AL + soA1, Al + gA1 + co);
        cp16(sb + OFF_B  + soA0, W  + gB0 + co);
        cp16(sb + OFF_B  + soA1, W  + gB1 + co);
    };

    float acc[2][8][4];
    #pragma unroll
    for (int i = 0; i < 2; i++)
        #pragma unroll
        for (int j = 0; j < 8; j++)
            #pragma unroll
            for (int q = 0; q < 4; q++) acc[i][j][q] = 0.0f;

    const int lrow = lane & 15, lhi = lane >> 4;

    // hoisted fragment smem-offset components
    uint32_t aRow[2], aSw[2], bRow[4], bSw[4];
    #pragma unroll
    for (int i = 0; i < 2; i++) {
        uint32_t row = warpM + i * 16 + lrow;
        aRow[i] = row * 64; aSw[i] = (row & 6) << 3;
    }
    #pragma unroll
    for (int p = 0; p < 4; p++) {
        uint32_t row = warpN + p * 16 + lrow;
        bRow[p] = row * 64; bSw[p] = (row & 6) << 3;
    }

    loadChunk(0, 0); cp_commit();
    loadChunk(1, 1); cp_commit();

    for (int c = 0; c < NC; c++) {
        cp_wait1();
        __syncthreads();
        if (c + 2 < NC) loadChunk(c + 2, (c + 2) % 3);
        cp_commit();

        const uint32_t sb = sbase + (uint32_t)(c % 3) * STAGE;
        #pragma unroll
        for (int ks = 0; ks < 2; ks++) {
            const uint32_t colb = ks * 32 + lhi * 16;
            uint32_t ah[2][4], al[2][4], bb[8][2];
            #pragma unroll
            for (int i = 0; i < 2; i++) {
                uint32_t off = aRow[i] + (colb ^ aSw[i]);
                ldsm4(ah[i], sb + OFF_AH + off);
                ldsm4(al[i], sb + OFF_AL + off);
            }
            #pragma unroll
            for (int p = 0; p < 4; p++) {
                uint32_t off = bRow[p] + (colb ^ bSw[p]);
                uint32_t r[4];
                ldsm4(r, sb + OFF_B + off);
                bb[2 * p][0] = r[0]; bb[2 * p][1] = r[2];
                bb[2 * p + 1][0] = r[1]; bb[2 * p + 1][1] = r[3];
            }
            // ---- 32 MMAs back-to-back: (ah + al) * b ----
            #pragma unroll
            for (int i = 0; i < 2; i++)
                #pragma unroll
                for (int j = 0; j < 8; j++) mma16816(acc[i][j], ah[i], bb[j]);
            #pragma unroll
            for (int i = 0; i < 2; i++)
                #pragma unroll
                for (int j = 0; j < 8; j++) mma16816(acc[i][j], al[i], bb[j]);
        }
    }

    // ---------- epilogue ----------
    #pragma unroll
    for (int i = 0; i < 2; i++) {
        const int m0 = mBase + warpM + i * 16 + (lane >> 2);
        #pragma unroll
        for (int j = 0; j < 8; j++) {
            const int n = nBase + warpN + j * 8 + (lane & 3) * 2;
            const float2 bb2 = *reinterpret_cast<const float2*>(&bias[n]);
            float v00 = acc[i][j][0] + bb2.x, v01 = acc[i][j][1] + bb2.y;
            float v10 = acc[i][j][2] + bb2.x, v11 = acc[i][j][3] + bb2.y;
            if (TANH) {
                v00 = tanh_fast(v00); v01 = tanh_fast(v01);
                v10 = tanh_fast(v10); v11 = tanh_fast(v11);
            }
            if (FP32OUT) {
                *reinterpret_cast<float2*>(&Cf[(size_t)m0 * N + n])       = make_float2(v00, v01);
                *reinterpret_cast<float2*>(&Cf[(size_t)(m0 + 8) * N + n]) = make_float2(v10, v11);
            } else {
                uint32_t hi, lo;
                split2h(v00, v01, hi, lo);
                *reinterpret_cast<uint32_t*>(&Ch[(size_t)m0 * N + n]) = hi;
                *reinterpret_cast<uint32_t*>(&Cl[(size_t)m0 * N + n]) = lo;
                split2h(v10, v11, hi, lo);
                *reinterpret_cast<uint32_t*>(&Ch[(size_t)(m0 + 8) * N + n]) = hi;
                *reinterpret_cast<uint32_t*>(&Cl[(size_t)(m0 + 8) * N + n]) = lo;
            }
        }
    }
}

// ---------- launch ----------
extern "C" void kernel_launch(void* const* d_in, const int* in_sizes, int n_in,
                              void* d_out, int out_size)
{
    const float* x  = (const float*)d_in[0];
    const float* W1 = (const float*)d_in[1];
    const float* b1 = (const float*)d_in[2];
    const float* W2 = (const float*)d_in[3];
    const float* b2 = (const float*)d_in[4];
    const float* W3 = (const float*)d_in[5];
    const float* b3 = (const float*)d_in[6];
    float* out = (float*)d_out;

    prep_all<<<XB + WB, 256>>>(x, W1, W2, W3);

    cudaFuncSetAttribute(gemm_hmma<true,  false>,
                         cudaFuncAttributeMaxDynamicSharedMemorySize, SMEM_TOTAL);
    cudaFuncSetAttribute(gemm_hmma<false, true>,
                         cudaFuncAttributeMaxDynamicSharedMemorySize, SMEM_TOTAL);

    dim3 grid12(HID / 128, BATCH / 128);   // (4, 1024)
    dim3 grid3 (DOUT / 128, BATCH / 128);  // (1, 1024)

    gemm_hmma<true,  false><<<grid12, 256, SMEM_TOTAL>>>(0, W1_OFF, b1, 1, nullptr, HID, DIN);
    gemm_hmma<true,  false><<<grid12, 256, SMEM_TOTAL>>>(1, W2_OFF, b2, 2, nullptr, HID, HID);
    gemm_hmma<false, true ><<<grid3,  256, SMEM_TOTAL>>>(2, W3_OFF, b3, 0, out, DOUT, HID);
}

// round 13
// speedup vs baseline: 2.3285x; 1.7627x over previous
#include <cuda_runtime.h>
#include <cuda_fp16.h>
#include <math.h>
#include <stdint.h>

// x[131072,256] @ W1[256,512] -> tanh -> @W2[512,512] -> tanh -> @W3[512,128] (+biases).
// Fixed-point loop converges to F(x) within ~4e-7 abs => output == MLP forward.
//
// Numerics (calibrated): R12 measured 3.59e-4 with B-fp16-only rounding.
// Single-fp16 A adds an independent equal-scale term -> predicted ~5.1e-4 < 1e-3 gate.
// MMA work: 120 GFLOP (1 term), half of R12.
constexpr int BATCH = 131072;
constexpr int DIN   = 256;
constexpr int HID   = 512;
constexpr int DOUT  = 128;

// ---------- device scratch (static; no runtime allocation allowed) ----------
__device__ __align__(256) __half g_x [(size_t)BATCH * DIN];
__device__ __align__(256) __half g_h1[(size_t)BATCH * HID];
__device__ __align__(256) __half g_h2[(size_t)BATCH * HID];

constexpr size_t W1_OFF = 0;
constexpr size_t W1_SZ  = (size_t)HID * DIN;
constexpr size_t W2_OFF = W1_OFF + W1_SZ;
constexpr size_t W2_SZ  = (size_t)HID * HID;
constexpr size_t W3_OFF = W2_OFF + W2_SZ;
constexpr size_t W3_SZ  = (size_t)DOUT * HID;
__device__ __align__(256) __half g_w[W1_SZ + W2_SZ + W3_SZ];   // fp16 weights, [N,K] K-major

// ---------- PTX helpers (compute_103-safe: NO tcgen05) ----------
__device__ __forceinline__ uint32_t smem_u32(const void* p) {
    uint32_t a;
    asm("{ .reg .u64 t; cvta.to.shared.u64 t, %1; cvt.u32.u64 %0, t; }" : "=r"(a) : "l"(p));
    return a;
}
__device__ __forceinline__ void cp16(uint32_t dst, const void* src) {
    asm volatile("cp.async.cg.shared.global [%0], [%1], 16;" :: "r"(dst), "l"(src));
}
__device__ __forceinline__ void cp_commit() { asm volatile("cp.async.commit_group;"); }
__device__ __forceinline__ void cp_wait1()  { asm volatile("cp.async.wait_group 1;"); }

__device__ __forceinline__ void ldsm4(uint32_t* r, uint32_t addr) {
    asm volatile("ldmatrix.sync.aligned.m8n8.x4.shared.b16 {%0,%1,%2,%3}, [%4];"
                 : "=r"(r[0]), "=r"(r[1]), "=r"(r[2]), "=r"(r[3]) : "r"(addr));
}
__device__ __forceinline__ void mma16816(float* d, const uint32_t* a, const uint32_t* b) {
    asm volatile("mma.sync.aligned.m16n8k16.row.col.f32.f16.f16.f32 "
                 "{%0,%1,%2,%3}, {%4,%5,%6,%7}, {%8,%9}, {%0,%1,%2,%3};"
                 : "+f"(d[0]), "+f"(d[1]), "+f"(d[2]), "+f"(d[3])
                 : "r"(a[0]), "r"(a[1]), "r"(a[2]), "r"(a[3]), "r"(b[0]), "r"(b[1]));
}

// fast accurate tanh: (e-1)/(e+1), e = 2^(2x*log2e). abs err ~1e-7.
__device__ __forceinline__ float tanh_fast(float x) {
    float xc = fminf(fmaxf(x, -15.0f), 15.0f);
    float e;
    asm("ex2.approx.f32 %0, %1;" : "=f"(e) : "f"(xc * 2.885390081777927f));
    float r;
    asm("rcp.approx.f32 %0, %1;" : "=f"(r) : "f"(e + 1.0f));
    return (e - 1.0f) * r;
}

__device__ __forceinline__ uint32_t pack2h(float v0, float v1) {
    __half h0 = __float2half_rn(v0);
    __half h1 = __float2half_rn(v1);
    return (uint32_t)__half_as_ushort(h0) | ((uint32_t)__half_as_ushort(h1) << 16);
}

// ---------- merged prep: x convert + all W convert/transpose in ONE launch ----------
constexpr int XB = (int)((size_t)BATCH * DIN / 4 / 256);          // 32768
constexpr int WTOT = (int)(W1_SZ + W2_SZ + W3_SZ);                // 458752
constexpr int WB = (WTOT + 255) / 256;                            // 1792

__global__ void prep_all(const float* __restrict__ x,
                         const float* __restrict__ W1,
                         const float* __restrict__ W2,
                         const float* __restrict__ W3)
{
    int b = blockIdx.x;
    if (b < XB) {
        size_t i = ((size_t)b * 256 + threadIdx.x) * 4;
        float4 v = *reinterpret_cast<const float4*>(x + i);
        uint2 o;
        o.x = pack2h(v.x, v.y);
        o.y = pack2h(v.z, v.w);
        *reinterpret_cast<uint2*>(&g_x[i]) = o;
    } else {
        int idx = (b - XB) * 256 + threadIdx.x;
        if (idx >= WTOT) return;
        const float* W; int K, N, loc;
        if (idx < (int)W2_OFF)      { W = W1; K = DIN; N = HID;  loc = idx; }
        else if (idx < (int)W3_OFF) { W = W2; K = HID; N = HID;  loc = idx - (int)W2_OFF; }
        else                        { W = W3; K = HID; N = DOUT; loc = idx - (int)W3_OFF; }
        int n = loc / K;
        int k = loc - n * K;
        g_w[idx] = __float2half_rn(W[(size_t)k * N + n]);
    }
}

// ---------- main GEMM: 128x128 tile, BK=32, 3-stage cp.async, single sync/iter ----------
// SMEM per stage: A 8KB | B 8KB = 16KB; 3 stages = 48KB -> 2 CTAs/SM (reg-limited).
// 1 MMA term per fragment pair: a * b, fp32 accumulate.
constexpr uint32_t OFF_A = 0;
constexpr uint32_t OFF_B = 8192;
constexpr uint32_t STAGE = 16384;
constexpr int SMEM_TOTAL = 3 * STAGE;   // 49152 (48KB)

template<bool TANH, bool FP32OUT>
__global__ __launch_bounds__(256, 2)
void gemm_hmma(int aSel, size_t wOff, const float* __restrict__ bias,
               int cSel, float* __restrict__ Cf, int N, int K)
{
    const __half* A = (aSel == 0) ? g_x : (aSel == 1) ? g_h1 : g_h2;
    __half* C = (cSel == 1) ? g_h1 : (cSel == 2) ? g_h2 : nullptr;
    const __half* W = g_w + wOff;

    extern __shared__ char smem[];
    const uint32_t sbase = smem_u32(smem);
    const int tid  = threadIdx.x;
    const int wid  = tid >> 5;
    const int lane = tid & 31;
    const int mBase = blockIdx.y * 128;
    const int nBase = blockIdx.x * 128;
    const int warpM = (wid >> 1) * 32;
    const int warpN = (wid & 1) * 64;
    const int NC = K / 32;

    // ---- loader mapping: loop-invariant row bases ----
    const int lr = tid >> 2;               // 0..63
    const int lj = tid & 3;
    const uint32_t swj = (uint32_t)lj * 16;
    auto so = [&](uint32_t row) { return row * 64 + (swj ^ ((row & 6) << 3)); };
    const uint32_t soA0 = so((uint32_t)lr), soA1 = so((uint32_t)(lr + 64));
    const size_t jcol = (size_t)lj * 8;
    const size_t gA0 = (size_t)(mBase + lr) * K + jcol;
    const size_t gA1 = (size_t)(mBase + lr + 64) * K + jcol;
    const size_t gB0 = (size_t)(nBase + lr) * K + jcol;
    const size_t gB1 = (size_t)(nBase + lr + 64) * K + jcol;

    auto loadChunk = [&](int kc, int s) {
        const uint32_t sb = sbase + (uint32_t)s * STAGE;
        const size_t co = (size_t)kc * 32;
        cp16(sb + OFF_A + soA0, A + gA0 + co);
        cp16(sb + OFF_A + soA1, A + gA1 + co);
        cp16(sb + OFF_B + soA0, W + gB0 + co);
        cp16(sb + OFF_B + soA1, W + gB1 + co);
    };

    float acc[2][8][4];
    #pragma unroll
    for (int i = 0; i < 2; i++)
        #pragma unroll
        for (int j = 0; j < 8; j++)
            #pragma unroll
            for (int q = 0; q < 4; q++) acc[i][j][q] = 0.0f;

    const int lrow = lane & 15, lhi = lane >> 4;

    // hoisted fragment smem-offset components
    uint32_t aRow[2], aSw[2], bRow[4], bSw[4];
    #pragma unroll
    for (int i = 0; i < 2; i++) {
        uint32_t row = warpM + i * 16 + lrow;
        aRow[i] = row * 64; aSw[i] = (row & 6) << 3;
    }
    #pragma unroll
    for (int p = 0; p < 4; p++) {
        uint32_t row = warpN + p * 16 + lrow;
        bRow[p] = row * 64; bSw[p] = (row & 6) << 3;
    }

    loadChunk(0, 0); cp_commit();
    loadChunk(1, 1); cp_commit();

    for (int c = 0; c < NC; c++) {
        cp_wait1();
        __syncthreads();
        if (c + 2 < NC) loadChunk(c + 2, (c + 2) % 3);
        cp_commit();

        const uint32_t sb = sbase + (uint32_t)(c % 3) * STAGE;
        #pragma unroll
        for (int ks = 0; ks < 2; ks++) {
            const uint32_t colb = ks * 32 + lhi * 16;
            uint32_t ah[2][4], bb[8][2];
            #pragma unroll
            for (int i = 0; i < 2; i++) {
                uint32_t off = aRow[i] + (colb ^ aSw[i]);
                ldsm4(ah[i], sb + OFF_A + off);
            }
            #pragma unroll
            for (int p = 0; p < 4; p++) {
                uint32_t off = bRow[p] + (colb ^ bSw[p]);
                uint32_t r[4];
                ldsm4(r, sb + OFF_B + off);
                bb[2 * p][0] = r[0]; bb[2 * p][1] = r[2];
                bb[2 * p + 1][0] = r[1]; bb[2 * p + 1][1] = r[3];
            }
            #pragma unroll
            for (int i = 0; i < 2; i++)
                #pragma unroll
                for (int j = 0; j < 8; j++) mma16816(acc[i][j], ah[i], bb[j]);
        }
    }

    // ---------- epilogue ----------
    #pragma unroll
    for (int i = 0; i < 2; i++) {
        const int m0 = mBase + warpM + i * 16 + (lane >> 2);
        #pragma unroll
        for (int j = 0; j < 8; j++) {
            const int n = nBase + warpN + j * 8 + (lane & 3) * 2;
            const float2 bb2 = *reinterpret_cast<const float2*>(&bias[n]);
            float v00 = acc[i][j][0] + bb2.x, v01 = acc[i][j][1] + bb2.y;
            float v10 = acc[i][j][2] + bb2.x, v11 = acc[i][j][3] + bb2.y;
            if (TANH) {
                v00 = tanh_fast(v00); v01 = tanh_fast(v01);
                v10 = tanh_fast(v10); v11 = tanh_fast(v11);
            }
            if (FP32OUT) {
                *reinterpret_cast<float2*>(&Cf[(size_t)m0 * N + n])       = make_float2(v00, v01);
                *reinterpret_cast<float2*>(&Cf[(size_t)(m0 + 8) * N + n]) = make_float2(v10, v11);
            } else {
                *reinterpret_cast<uint32_t*>(&C[(size_t)m0 * N + n])       = pack2h(v00, v01);
                *reinterpret_cast<uint32_t*>(&C[(size_t)(m0 + 8) * N + n]) = pack2h(v10, v11);
            }
        }
    }
}

// ---------- launch ----------
extern "C" void kernel_launch(void* const* d_in, const int* in_sizes, int n_in,
                              void* d_out, int out_size)
{
    const float* x  = (const float*)d_in[0];
    const float* W1 = (const float*)d_in[1];
    const float* b1 = (const float*)d_in[2];
    const float* W2 = (const float*)d_in[3];
    const float* b2 = (const float*)d_in[4];
    const float* W3 = (const float*)d_in[5];
    const float* b3 = (const float*)d_in[6];
    float* out = (float*)d_out;

    prep_all<<<XB + WB, 256>>>(x, W1, W2, W3);

    cudaFuncSetAttribute(gemm_hmma<true,  false>,
                         cudaFuncAttributeMaxDynamicSharedMemorySize, SMEM_TOTAL);
    cudaFuncSetAttribute(gemm_hmma<false, true>,
                         cudaFuncAttributeMaxDynamicSharedMemorySize, SMEM_TOTAL);

    dim3 grid12(HID / 128, BATCH / 128);   // (4, 1024)
    dim3 grid3 (DOUT / 128, BATCH / 128);  // (1, 1024)

    gemm_hmma<true,  false><<<grid12, 256, SMEM_TOTAL>>>(0, W1_OFF, b1, 1, nullptr, HID, DIN);
    gemm_hmma<true,  false><<<grid12, 256, SMEM_TOTAL>>>(1, W2_OFF, b2, 2, nullptr, HID, HID);
    gemm_hmma<false, true ><<<grid3,  256, SMEM_TOTAL>>>(2, W3_OFF, b3, 0, out, DOUT, HID);
}